// round 2
// baseline (speedup 1.0000x reference)
#include <cuda_runtime.h>
#include <cuda_bf16.h>

// HONU order-2: out[i] = sum_{j<=k} W[p(j,k)] * x[i,j] * x[i,k] + b
// p(j,k) = j*64 - j*(j-1)/2 + (k-j)
//
// Round 2: 4 threads per row (j split by j mod 4 -> perfectly balanced 136
// float4 inner iterations per lane), shfl.bfly reduction. A at stride 68
// floats so the 4 lanes' LDS.128 hit disjoint bank quads. 128-thread blocks,
// 32 rows/block, 512 blocks (~3.5 warps/SMSP).

#define LDIM 64
#define ASTRIDE 68              // floats; 16B-aligned, banks +4 per row
#define ROWS_PER_BLOCK 32
#define THREADS 128

__global__ void __launch_bounds__(THREADS) honu_kernel(
    const float* __restrict__ x, const float* __restrict__ W,
    const float* __restrict__ b, float* __restrict__ out)
{
    __shared__ __align__(16) float A[LDIM * ASTRIDE];        // 17.0 KB
    __shared__ float xs[ROWS_PER_BLOCK * (LDIM + 1)];        // 8.1 KB, stride 65

    const int tid  = threadIdx.x;
    const int lane = tid & 31;
    const int wrp  = tid >> 5;
    const int t    = lane & 3;                 // j-parity slot 0..3
    const int r    = (wrp << 3) + (lane >> 2); // local row 0..31
    const int row0 = blockIdx.x * ROWS_PER_BLOCK;

    // --- Build zero-filled upper-triangular A (stride 68) from packed W
    for (int i = tid; i < LDIM * LDIM; i += THREADS) {
        int j = i >> 6, k = i & 63;
        int off = j * LDIM - (j * (j - 1)) / 2;
        A[j * ASTRIDE + k] = (k >= j) ? W[off + (k - j)] : 0.0f;
    }

    // --- Stage 32x64 x tile: coalesced float4 loads, padded smem stores
    {
        const float4* xg4 = reinterpret_cast<const float4*>(x + (size_t)row0 * LDIM);
        #pragma unroll
        for (int it = 0; it < 4; ++it) {
            int i  = it * THREADS + tid;       // 0..511 float4s
            int rr = i >> 4;
            int c4 = i & 15;
            float4 v = xg4[i];
            xs[rr * 65 + c4 * 4 + 0] = v.x;
            xs[rr * 65 + c4 * 4 + 1] = v.y;
            xs[rr * 65 + c4 * 4 + 2] = v.z;
            xs[rr * 65 + c4 * 4 + 3] = v.w;
        }
    }
    __syncthreads();

    // --- Row into registers (broadcast within lane-quads, rows bank-staggered)
    float xr[LDIM];
    #pragma unroll
    for (int c = 0; c < LDIM; ++c) xr[c] = xs[r * 65 + c];

    // --- Quadratic form, j = 4*jj + t. Inner float4 span q = jj..15 is
    //     identical for all 4 lanes of a quad -> perfect balance.
    const float4* A4 = reinterpret_cast<const float4*>(A);  // row stride 17
    float acc = 0.0f;
    #pragma unroll
    for (int jj = 0; jj < 16; ++jj) {
        const int j = 4 * jj + t;
        float i0 = 0.0f, i1 = 0.0f, i2 = 0.0f, i3 = 0.0f;
        #pragma unroll
        for (int q = jj; q < 16; ++q) {
            float4 w = A4[j * 17 + q];
            i0 = fmaf(w.x, xr[4 * q + 0], i0);
            i1 = fmaf(w.y, xr[4 * q + 1], i1);
            i2 = fmaf(w.z, xr[4 * q + 2], i2);
            i3 = fmaf(w.w, xr[4 * q + 3], i3);
        }
        acc = fmaf(xr[j], (i0 + i1) + (i2 + i3), acc);
    }

    // --- Reduce the 4 lane-partials of each row
    acc += __shfl_xor_sync(0xffffffffu, acc, 1);
    acc += __shfl_xor_sync(0xffffffffu, acc, 2);

    if (t == 0) out[row0 + r] = acc + b[0];
}

extern "C" void kernel_launch(void* const* d_in, const int* in_sizes, int n_in,
                              void* d_out, int out_size) {
    const float* x = (const float*)d_in[0];   // (16384, 64) f32
    const float* W = (const float*)d_in[1];   // (2145,)  f32 (first 2080 used)
    const float* b = (const float*)d_in[2];   // (1,)     f32
    float*     out = (float*)d_out;           // (16384,) f32

    const int nrows  = out_size;                          // 16384
    const int blocks = (nrows + ROWS_PER_BLOCK - 1) / ROWS_PER_BLOCK;  // 512
    honu_kernel<<<blocks, THREADS>>>(x, W, b, out);
}

// round 3
// speedup vs baseline: 1.1805x; 1.1805x over previous
#include <cuda_runtime.h>
#include <cuda_bf16.h>
#include <cstdint>

// HONU order-2: out[i] = sum_{j<=k} W[p(j,k)] * x[i,j] * x[i,k] + b
// p(j,k) = j*64 - j*(j-1)/2 + (k-j)
//
// Round 3: 4 lanes per row (j = 4*jj + t, balanced 136 float4 iters/lane).
// Both operands streamed from shared via ld.shared.v2.b64 (no 64-reg row
// array -> regs ~35, deep LDS pipelining, immediate-offset addressing).
// Math in packed fma.rn.f32x2 (half the FFMA issue count). Strides of 68
// floats keep every LDS.128-class access conflict-free.

#define LDIM 64
#define AST  68                 // float stride (272 B, 16B-aligned)
#define ROWS_PER_BLOCK 32
#define THREADS 128

__device__ __forceinline__ void lds_v2u64(uint64_t& a, uint64_t& b, unsigned addr) {
    asm volatile("ld.shared.v2.b64 {%0,%1}, [%2];" : "=l"(a), "=l"(b) : "r"(addr));
}
__device__ __forceinline__ void fma2(uint64_t& d, uint64_t a, uint64_t b) {
    asm volatile("fma.rn.f32x2 %0, %1, %2, %0;" : "+l"(d) : "l"(a), "l"(b));
}
__device__ __forceinline__ uint64_t add2(uint64_t a, uint64_t b) {
    uint64_t d;
    asm volatile("add.rn.f32x2 %0, %1, %2;" : "=l"(d) : "l"(a), "l"(b));
    return d;
}

__global__ void __launch_bounds__(THREADS) honu_kernel(
    const float* __restrict__ x, const float* __restrict__ W,
    const float* __restrict__ b, float* __restrict__ out)
{
    __shared__ __align__(16) float A[LDIM * AST];              // 17.0 KB
    __shared__ __align__(16) float xs[ROWS_PER_BLOCK * AST];   // 8.5 KB

    const int tid  = threadIdx.x;
    const int lane = tid & 31;
    const int t    = lane & 3;                  // j mod 4 slot
    const int r    = ((tid >> 5) << 3) + (lane >> 2);   // local row 0..31
    const int row0 = blockIdx.x * ROWS_PER_BLOCK;

    // --- Build zero-filled upper-triangular A (stride 68) from packed W
    for (int i = tid; i < LDIM * LDIM; i += THREADS) {
        int j = i >> 6, k = i & 63;
        int off = j * LDIM - (j * (j - 1)) / 2;
        A[j * AST + k] = (k >= j) ? W[off + (k - j)] : 0.0f;
    }

    // --- Stage 32x64 x tile (float4 in, float4 out, stride 17 float4s)
    {
        const float4* xg4 = reinterpret_cast<const float4*>(x + (size_t)row0 * LDIM);
        float4*       xs4 = reinterpret_cast<float4*>(xs);
        #pragma unroll
        for (int it = 0; it < 4; ++it) {
            int i  = it * THREADS + tid;        // 0..511
            int rr = i >> 4;
            int c4 = i & 15;
            xs4[rr * 17 + c4] = xg4[i];
        }
    }
    __syncthreads();

    // --- Shared-memory byte addresses (immediate-offset friendly)
    const unsigned xs_a = (unsigned)__cvta_generic_to_shared(xs) + r * (AST * 4);
    const unsigned A_a  = (unsigned)__cvta_generic_to_shared(A)  + t * (AST * 4);

    // --- Quadratic form: j = 4*jj + t; inner over float4 chunks q = jj..15.
    uint64_t acc = 0;                            // packed f32x2 accumulator
    #pragma unroll
    for (int jj = 0; jj < 16; ++jj) {
        const unsigned wrow = A_a + jj * (4 * AST * 4);   // row j = 4jj+t
        uint64_t i01 = 0, i23 = 0;
        #pragma unroll
        for (int q = jj; q < 16; ++q) {
            uint64_t w01, w23, x01, x23;
            lds_v2u64(w01, w23, wrow + q * 16);
            lds_v2u64(x01, x23, xs_a + q * 16);
            fma2(i01, w01, x01);
            fma2(i23, w23, x23);
        }
        // x_j broadcast into both halves, packed outer FMA
        float xj = xs[r * AST + 4 * jj + t];
        uint64_t xj2;
        asm volatile("mov.b64 %0, {%1,%1};" : "=l"(xj2) : "r"(__float_as_uint(xj)));
        fma2(acc, xj2, add2(i01, i23));
    }

    // --- Unpack, reduce the 4 lane-partials of the row
    uint32_t lo, hi;
    asm volatile("mov.b64 {%0,%1}, %2;" : "=r"(lo), "=r"(hi) : "l"(acc));
    float a = __uint_as_float(lo) + __uint_as_float(hi);
    a += __shfl_xor_sync(0xffffffffu, a, 1);
    a += __shfl_xor_sync(0xffffffffu, a, 2);

    if (t == 0) out[row0 + r] = a + b[0];
}

extern "C" void kernel_launch(void* const* d_in, const int* in_sizes, int n_in,
                              void* d_out, int out_size) {
    const float* x = (const float*)d_in[0];   // (16384, 64) f32
    const float* W = (const float*)d_in[1];   // (2145,)  f32 (first 2080 used)
    const float* b = (const float*)d_in[2];   // (1,)     f32
    float*     out = (float*)d_out;           // (16384,) f32

    const int nrows  = out_size;                                       // 16384
    const int blocks = (nrows + ROWS_PER_BLOCK - 1) / ROWS_PER_BLOCK;  // 512
    honu_kernel<<<blocks, THREADS>>>(x, W, b, out);
}